// round 1
// baseline (speedup 1.0000x reference)
#include <cuda_runtime.h>
#include <math.h>

#define D_MODEL 1024
#define D_FF    4096
#define N_HEADS 16
#define SEQ     1000
#define BATCH   8
#define M_ROWS  (BATCH * SEQ)   // 8000

// ---------------- scratch (static device globals; no allocation) ----------------
__device__ float g_h  [M_ROWS * D_MODEL];
__device__ float g_q  [M_ROWS * D_MODEL];
__device__ float g_k  [M_ROWS * D_MODEL];
__device__ float g_v  [M_ROWS * D_MODEL];
__device__ float g_att[M_ROWS * D_MODEL];
__device__ float g_x1 [M_ROWS * D_MODEL];
__device__ float g_h2 [M_ROWS * D_MODEL];
__device__ float g_ff [M_ROWS * D_FF];

// ---------------- LayerNorm: one block (256 thr) per row of 1024 ----------------
__global__ void ln_kernel(const float* __restrict__ x, const float* __restrict__ g,
                          const float* __restrict__ bt, float* __restrict__ out) {
    int row = blockIdx.x;
    int t = threadIdx.x;                           // 256 threads, 1 float4 each
    const float4* xr = (const float4*)(x + (size_t)row * D_MODEL);
    float4 v = xr[t];
    float s  = v.x + v.y + v.z + v.w;
    float sq = v.x * v.x + v.y * v.y + v.z * v.z + v.w * v.w;
    #pragma unroll
    for (int o = 16; o > 0; o >>= 1) {
        s  += __shfl_xor_sync(0xffffffffu, s,  o);
        sq += __shfl_xor_sync(0xffffffffu, sq, o);
    }
    __shared__ float ss[8], ssq[8];
    int w = t >> 5;
    if ((t & 31) == 0) { ss[w] = s; ssq[w] = sq; }
    __syncthreads();
    float tot = 0.f, totq = 0.f;
    #pragma unroll
    for (int i = 0; i < 8; i++) { tot += ss[i]; totq += ssq[i]; }
    float mean = tot * (1.f / D_MODEL);
    float var  = totq * (1.f / D_MODEL) - mean * mean;
    float rstd = rsqrtf(var + 1e-5f);
    float4 gg = ((const float4*)g)[t];
    float4 bb = ((const float4*)bt)[t];
    float4 o;
    o.x = (v.x - mean) * rstd * gg.x + bb.x;
    o.y = (v.y - mean) * rstd * gg.y + bb.y;
    o.z = (v.z - mean) * rstd * gg.z + bb.z;
    o.w = (v.w - mean) * rstd * gg.w + bb.w;
    ((float4*)(out + (size_t)row * D_MODEL))[t] = o;
}

// ---------------- SGEMM: C = epi(A@B), 128x128 tile, BK=8, 256 thr, 8x8/thr ------
// EPI: 0 = plain, 1 = + bias + residual, 2 = gelu(+ bias)
__device__ __forceinline__ float gelu_exact(float x) {
    return 0.5f * x * (1.0f + erff(x * 0.70710678118654752f));
}

template<int EPI>
__global__ __launch_bounds__(256)
void sgemm_kernel(const float* __restrict__ A, const float* __restrict__ B,
                  float* __restrict__ C, int M, int N, int K,
                  const float* __restrict__ bias, const float* __restrict__ res) {
    __shared__ float As[8][128];
    __shared__ float Bs[8][128];
    int tid = threadIdx.x;
    int bm = blockIdx.y, bn = blockIdx.x;

    int arow = tid >> 1;             // 0..127
    int acol = (tid & 1) * 4;        // 0 or 4
    int brow = tid >> 5;             // 0..7
    int bcol = (tid & 31) * 4;       // 0..124

    int grow = bm * 128 + arow;
    bool aval = grow < M;
    const float* Aptr = A + (size_t)(aval ? grow : 0) * K + acol;
    const float* Bptr = B + (size_t)brow * N + bn * 128 + bcol;

    int tx = (tid & 15) * 8;         // col offset in tile
    int ty = (tid >> 4) * 8;         // row offset in tile

    float c[8][8];
    #pragma unroll
    for (int i = 0; i < 8; i++)
        #pragma unroll
        for (int j = 0; j < 8; j++) c[i][j] = 0.f;

    for (int k0 = 0; k0 < K; k0 += 8) {
        float4 a  = aval ? *(const float4*)Aptr : make_float4(0.f, 0.f, 0.f, 0.f);
        float4 bv = *(const float4*)Bptr;
        As[acol + 0][arow] = a.x;
        As[acol + 1][arow] = a.y;
        As[acol + 2][arow] = a.z;
        As[acol + 3][arow] = a.w;
        *(float4*)&Bs[brow][bcol] = bv;
        __syncthreads();
        #pragma unroll
        for (int kk = 0; kk < 8; kk++) {
            float ar[8], br[8];
            *(float4*)&ar[0] = *(const float4*)&As[kk][ty];
            *(float4*)&ar[4] = *(const float4*)&As[kk][ty + 4];
            *(float4*)&br[0] = *(const float4*)&Bs[kk][tx];
            *(float4*)&br[4] = *(const float4*)&Bs[kk][tx + 4];
            #pragma unroll
            for (int i = 0; i < 8; i++)
                #pragma unroll
                for (int j = 0; j < 8; j++)
                    c[i][j] += ar[i] * br[j];
        }
        __syncthreads();
        Aptr += 8;
        Bptr += (size_t)8 * N;
    }

    // epilogue
    #pragma unroll
    for (int i = 0; i < 8; i++) {
        int r = bm * 128 + ty + i;
        if (r >= M) continue;
        #pragma unroll
        for (int j0 = 0; j0 < 8; j0 += 4) {
            int col = bn * 128 + tx + j0;
            float4 o;
            float vals[4];
            #pragma unroll
            for (int jj = 0; jj < 4; jj++) {
                float vv = c[i][j0 + jj];
                if (EPI >= 1) vv += bias[col + jj];
                if (EPI == 1) vv += res[(size_t)r * N + col + jj];
                if (EPI == 2) vv = gelu_exact(vv);
                vals[jj] = vv;
            }
            o.x = vals[0]; o.y = vals[1]; o.z = vals[2]; o.w = vals[3];
            *(float4*)&C[(size_t)r * N + col] = o;
        }
    }
}

// ---------------- Flash attention (causal), 64 q-rows/block, 128 threads ---------
// thread t: row r = t>>1 (0..63), half = t&1 (cols/dims 0..31 or 32..63)
#define ATTN_SMEM ((4096 + 4096 + 64 * 65) * 4)

__global__ __launch_bounds__(128)
void attn_kernel(const float* __restrict__ Q, const float* __restrict__ K,
                 const float* __restrict__ V, float* __restrict__ O) {
    extern __shared__ float sm[];
    float* Ks = sm;              // 64 x 64
    float* Vs = sm + 4096;       // 64 x 64
    float* Ps = sm + 8192;       // 64 x 65 (padded)

    const int t    = threadIdx.x;
    const int r    = t >> 1;
    const int half = t & 1;
    const int iTile = blockIdx.x;        // 0..15
    const int bh = blockIdx.y;           // 0..127
    const int b = bh >> 4, h = bh & 15;
    const int qi = iTile * 64 + r;
    const bool qvalid = qi < SEQ;

    // Q row in registers (64 floats)
    float4 q4[16];
    const float* qptr = Q + (size_t)(b * SEQ + (qvalid ? qi : 0)) * D_MODEL + h * 64;
    #pragma unroll
    for (int i = 0; i < 16; i++) q4[i] = ((const float4*)qptr)[i];

    float acc[32];
    #pragma unroll
    for (int i = 0; i < 32; i++) acc[i] = 0.f;
    float m = -INFINITY, l = 0.f;
    const float scale = 0.125f;          // 1/sqrt(64)

    for (int j = 0; j <= iTile; j++) {
        __syncthreads();   // protect Vs/Ps reads of previous iteration
        // load K & V tiles (each thread: 8 float4s of each)
        #pragma unroll
        for (int it = 0; it < 8; it++) {
            int lin = it * 128 + t;      // 0..1023
            int rr  = lin >> 4;          // 0..63
            int d4  = (lin & 15) << 2;   // 0..60
            int kj  = j * 64 + rr;
            float4 kv, vv;
            if (kj < SEQ) {
                size_t base = (size_t)(b * SEQ + kj) * D_MODEL + h * 64 + d4;
                kv = *(const float4*)(K + base);
                vv = *(const float4*)(V + base);
            } else {
                kv = make_float4(0.f, 0.f, 0.f, 0.f);
                vv = kv;
            }
            *(float4*)&Ks[rr * 64 + d4] = kv;
            *(float4*)&Vs[rr * 64 + d4] = vv;
        }
        __syncthreads();

        // stage A: scores + online softmax for this thread's 32 columns
        float s[32];
        #pragma unroll
        for (int cc = 0; cc < 32; cc++) {
            int c = half * 32 + cc;
            const float4* kr = (const float4*)&Ks[c * 64];
            float a0 = 0.f;
            #pragma unroll
            for (int d = 0; d < 16; d++) {
                float4 kk = kr[d];
                a0 += q4[d].x * kk.x + q4[d].y * kk.y + q4[d].z * kk.z + q4[d].w * kk.w;
            }
            int col = j * 64 + c;
            s[cc] = (col <= qi) ? a0 * scale : -INFINITY;
        }
        float tmax = -INFINITY;
        #pragma unroll
        for (int cc = 0; cc < 32; cc++) tmax = fmaxf(tmax, s[cc]);
        tmax = fmaxf(tmax, __shfl_xor_sync(0xffffffffu, tmax, 1));
        float mnew  = fmaxf(m, tmax);
        float alpha = __expf(m - mnew);
        float psum = 0.f;
        #pragma unroll
        for (int cc = 0; cc < 32; cc++) {
            float p = __expf(s[cc] - mnew);
            psum += p;
            Ps[r * 65 + half * 32 + cc] = p;
        }
        psum += __shfl_xor_sync(0xffffffffu, psum, 1);
        l = l * alpha + psum;
        m = mnew;
        __syncthreads();

        // stage B: O = O*alpha + P @ V   (this thread's 32 output dims)
        #pragma unroll
        for (int dd = 0; dd < 32; dd++) acc[dd] *= alpha;
        #pragma unroll 4
        for (int c = 0; c < 64; c++) {
            float p = Ps[r * 65 + c];
            const float4* vr = (const float4*)&Vs[c * 64 + half * 32];
            #pragma unroll
            for (int d8 = 0; d8 < 8; d8++) {
                float4 vv = vr[d8];
                acc[d8 * 4 + 0] += p * vv.x;
                acc[d8 * 4 + 1] += p * vv.y;
                acc[d8 * 4 + 2] += p * vv.z;
                acc[d8 * 4 + 3] += p * vv.w;
            }
        }
    }

    if (qvalid) {
        float inv = 1.f / l;
        float* op = O + (size_t)(b * SEQ + qi) * D_MODEL + h * 64 + half * 32;
        #pragma unroll
        for (int d8 = 0; d8 < 8; d8++) {
            float4 o;
            o.x = acc[d8 * 4 + 0] * inv;
            o.y = acc[d8 * 4 + 1] * inv;
            o.z = acc[d8 * 4 + 2] * inv;
            o.w = acc[d8 * 4 + 3] * inv;
            ((float4*)op)[d8] = o;
        }
    }
}

// ---------------- launch ----------------
extern "C" void kernel_launch(void* const* d_in, const int* in_sizes, int n_in,
                              void* d_out, int out_size) {
    const float* x     = (const float*)d_in[0];
    const float* wq    = (const float*)d_in[1];
    const float* wk    = (const float*)d_in[2];
    const float* wv    = (const float*)d_in[3];
    const float* wo    = (const float*)d_in[4];
    const float* bo    = (const float*)d_in[5];
    const float* w1    = (const float*)d_in[6];
    const float* b1    = (const float*)d_in[7];
    const float* w2    = (const float*)d_in[8];
    const float* b2    = (const float*)d_in[9];
    const float* gg1   = (const float*)d_in[10];
    const float* be1   = (const float*)d_in[11];
    const float* gg2   = (const float*)d_in[12];
    const float* be2   = (const float*)d_in[13];
    float* out = (float*)d_out;

    float *ph, *pq, *pk, *pv, *patt, *px1, *ph2, *pff;
    cudaGetSymbolAddress((void**)&ph,   g_h);
    cudaGetSymbolAddress((void**)&pq,   g_q);
    cudaGetSymbolAddress((void**)&pk,   g_k);
    cudaGetSymbolAddress((void**)&pv,   g_v);
    cudaGetSymbolAddress((void**)&patt, g_att);
    cudaGetSymbolAddress((void**)&px1,  g_x1);
    cudaGetSymbolAddress((void**)&ph2,  g_h2);
    cudaGetSymbolAddress((void**)&pff,  g_ff);

    cudaFuncSetAttribute(attn_kernel, cudaFuncAttributeMaxDynamicSharedMemorySize, ATTN_SMEM);

    dim3 gD(D_MODEL / 128, (M_ROWS + 127) / 128);   // (8, 63)
    dim3 gF(D_FF   / 128, (M_ROWS + 127) / 128);    // (32, 63)

    // 1. h = LN(x)
    ln_kernel<<<M_ROWS, 256>>>(x, gg1, be1, ph);
    // 2-4. Q,K,V = h @ Wq/Wk/Wv
    sgemm_kernel<0><<<gD, 256>>>(ph, wq, pq, M_ROWS, D_MODEL, D_MODEL, nullptr, nullptr);
    sgemm_kernel<0><<<gD, 256>>>(ph, wk, pk, M_ROWS, D_MODEL, D_MODEL, nullptr, nullptr);
    sgemm_kernel<0><<<gD, 256>>>(ph, wv, pv, M_ROWS, D_MODEL, D_MODEL, nullptr, nullptr);
    // 5. causal flash attention
    attn_kernel<<<dim3(16, BATCH * N_HEADS), 128, ATTN_SMEM>>>(pq, pk, pv, patt);
    // 6. x1 = x + att @ Wo + bo
    sgemm_kernel<1><<<gD, 256>>>(patt, wo, px1, M_ROWS, D_MODEL, D_MODEL, bo, x);
    // 7. h2 = LN(x1)
    ln_kernel<<<M_ROWS, 256>>>(px1, gg2, be2, ph2);
    // 8. ff = gelu(h2 @ W1 + b1)
    sgemm_kernel<2><<<gF, 256>>>(ph2, w1, pff, M_ROWS, D_FF, D_MODEL, b1, nullptr);
    // 9. out = x1 + ff @ W2 + b2
    sgemm_kernel<1><<<gD, 256>>>(pff, w2, out, M_ROWS, D_MODEL, D_FF, b2, px1);
}

// round 3
// speedup vs baseline: 3.2438x; 3.2438x over previous
#include <cuda_runtime.h>
#include <cuda_fp16.h>
#include <math.h>
#include <stdint.h>

#define D_MODEL 1024
#define D_FF    4096
#define N_HEADS 16
#define SEQ     1000
#define BATCH   8
#define M_ROWS  (BATCH * SEQ)   // 8000

// ---------------- scratch (static device globals; no allocation) ----------------
__device__ float g_q  [M_ROWS * D_MODEL];
__device__ float g_k  [M_ROWS * D_MODEL];
__device__ float g_v  [M_ROWS * D_MODEL];
__device__ float g_x1 [M_ROWS * D_MODEL];
__device__ __half g_a16[M_ROWS * D_FF];    // h16 / att16 / h2_16 (sequential reuse)
__device__ __half g_b16[M_ROWS * D_FF];    // ff16
__device__ __half g_wq16[D_MODEL * D_MODEL];
__device__ __half g_wk16[D_MODEL * D_MODEL];
__device__ __half g_wv16[D_MODEL * D_MODEL];
__device__ __half g_wo16[D_MODEL * D_MODEL];
__device__ __half g_w116[D_FF * D_MODEL];   // [N=4096][K=1024]
__device__ __half g_w216[D_MODEL * D_FF];   // [N=1024][K=4096]

// ---------------- PTX helpers (all sm_80-era, compile on compute_103) ------------
__device__ __forceinline__ uint32_t smem_u32(const void* p) {
    uint32_t a;
    asm("{ .reg .u64 t; cvta.to.shared.u64 t, %1; cvt.u32.u64 %0, t; }" : "=r"(a) : "l"(p));
    return a;
}
__device__ __forceinline__ void cp16(uint32_t dst, const void* src) {
    asm volatile("cp.async.cg.shared.global [%0], [%1], 16;" :: "r"(dst), "l"(src));
}
__device__ __forceinline__ void ldm_x4(uint32_t& r0, uint32_t& r1, uint32_t& r2, uint32_t& r3,
                                       uint32_t addr) {
    asm volatile("ldmatrix.sync.aligned.m8n8.x4.shared.b16 {%0,%1,%2,%3}, [%4];"
                 : "=r"(r0), "=r"(r1), "=r"(r2), "=r"(r3) : "r"(addr));
}
__device__ __forceinline__ void mma16816(float* c, const uint32_t* a, const uint32_t* b) {
    asm volatile(
        "mma.sync.aligned.m16n8k16.row.col.f32.f16.f16.f32 "
        "{%0,%1,%2,%3}, {%4,%5,%6,%7}, {%8,%9}, {%0,%1,%2,%3};"
        : "+f"(c[0]), "+f"(c[1]), "+f"(c[2]), "+f"(c[3])
        : "r"(a[0]), "r"(a[1]), "r"(a[2]), "r"(a[3]), "r"(b[0]), "r"(b[1]));
}
__device__ __forceinline__ float gelu_exact(float x) {
    return 0.5f * x * (1.0f + erff(x * 0.70710678118654752f));
}

// ---------------- LayerNorm -> fp16 out ----------------
__global__ void ln16_kernel(const float* __restrict__ x, const float* __restrict__ g,
                            const float* __restrict__ bt, __half* __restrict__ out) {
    int row = blockIdx.x;
    int t = threadIdx.x;
    const float4* xr = (const float4*)(x + (size_t)row * D_MODEL);
    float4 v = xr[t];
    float s  = v.x + v.y + v.z + v.w;
    float sq = v.x * v.x + v.y * v.y + v.z * v.z + v.w * v.w;
    #pragma unroll
    for (int o = 16; o > 0; o >>= 1) {
        s  += __shfl_xor_sync(0xffffffffu, s,  o);
        sq += __shfl_xor_sync(0xffffffffu, sq, o);
    }
    __shared__ float ss[8], ssq[8];
    int w = t >> 5;
    if ((t & 31) == 0) { ss[w] = s; ssq[w] = sq; }
    __syncthreads();
    float tot = 0.f, totq = 0.f;
    #pragma unroll
    for (int i = 0; i < 8; i++) { tot += ss[i]; totq += ssq[i]; }
    float mean = tot * (1.f / D_MODEL);
    float var  = totq * (1.f / D_MODEL) - mean * mean;
    float rstd = rsqrtf(var + 1e-5f);
    float4 gg = ((const float4*)g)[t];
    float4 bb = ((const float4*)bt)[t];
    float o0 = (v.x - mean) * rstd * gg.x + bb.x;
    float o1 = (v.y - mean) * rstd * gg.y + bb.y;
    float o2 = (v.z - mean) * rstd * gg.z + bb.z;
    float o3 = (v.w - mean) * rstd * gg.w + bb.w;
    __half2* op = (__half2*)(out + (size_t)row * D_MODEL);
    op[2 * t + 0] = __floats2half2_rn(o0, o1);
    op[2 * t + 1] = __floats2half2_rn(o2, o3);
}

// ---------------- weight transpose + convert: W[K,N] fp32 -> Wt[N,K] fp16 --------
__global__ void wcvt_kernel(const float* __restrict__ W, __half* __restrict__ Wt,
                            int K, int N) {
    __shared__ float t[32][33];
    int k0 = blockIdx.x * 32, n0 = blockIdx.y * 32;
    int tx = threadIdx.x, ty = threadIdx.y;     // (32, 8)
    #pragma unroll
    for (int r = 0; r < 32; r += 8)
        t[ty + r][tx] = W[(size_t)(k0 + ty + r) * N + n0 + tx];
    __syncthreads();
    #pragma unroll
    for (int r = 0; r < 32; r += 8)
        Wt[(size_t)(n0 + ty + r) * K + k0 + tx] = __float2half(t[tx][ty + r]);
}

// ---------------- fp16 tensor-core GEMM: C = epi(A @ Bt^T) -----------------------
// A: [M,K] fp16 row-major. Bt: [N,K] fp16 row-major. 128x128 tile, BK=32.
// 256 threads = 8 warps as 4(m) x 2(n); warp tile 32x64.
// EPI: 0 = plain fp32 out, 1 = +bias+res fp32 out, 2 = gelu(+bias) fp16 out.
#define ROWB 80   // padded smem row bytes (32 halfs = 64B data + 16B pad)

template<int EPI>
__global__ void __launch_bounds__(256, 2)
mma_gemm(const __half* __restrict__ A, const __half* __restrict__ Bt,
         float* __restrict__ C, __half* __restrict__ C16, int M, int N, int K,
         const float* __restrict__ bias, const float* __restrict__ res) {
    __shared__ __align__(128) char sA[2][128 * ROWB];
    __shared__ __align__(128) char sB[2][128 * ROWB];

    const int tid = threadIdx.x;
    const int lid = tid & 31;
    const int wid = tid >> 5;
    const int wm = wid & 3, wn = wid >> 2;
    const int bm = blockIdx.y, bn = blockIdx.x;

    uint32_t uA[2], uB[2];
    uA[0] = smem_u32(sA[0]); uA[1] = smem_u32(sA[1]);
    uB[0] = smem_u32(sB[0]); uB[1] = smem_u32(sB[1]);

    // loader indices: 512 16B chunks per tile, 2 per thread
    const int r0i = tid >> 2, c0i = tid & 3;              // chunk ids tid, tid+256
    const int r1i = (tid + 256) >> 2, c1i = tid & 3;      // (tid+256)&3 == tid&3

    // ldmatrix lane addressing
    const int part = lid >> 3;
    const int aRow  = wm * 32 + (part & 1) * 8 + (lid & 7);   // + f*16
    const int aColB = ((part >> 1) & 1) * 16;                 // + ks*32
    const int bRow  = wn * 64 + ((part >> 1) & 1) * 8 + (lid & 7);  // + p*16
    const int bColB = (part & 1) * 16;                        // + ks*32

    float acc[2][8][4];
    #pragma unroll
    for (int f = 0; f < 2; f++)
        #pragma unroll
        for (int q = 0; q < 8; q++)
            #pragma unroll
            for (int z = 0; z < 4; z++) acc[f][q][z] = 0.f;

    const int NC = K >> 5;

    // tile loader (cp.async)
    auto loadTile = [&](int s, int k0) {
        int gr0 = bm * 128 + r0i; if (gr0 >= M) gr0 = M - 1;
        int gr1 = bm * 128 + r1i; if (gr1 >= M) gr1 = M - 1;
        cp16(uA[s] + r0i * ROWB + c0i * 16, A + (size_t)gr0 * K + k0 + c0i * 8);
        cp16(uA[s] + r1i * ROWB + c1i * 16, A + (size_t)gr1 * K + k0 + c1i * 8);
        cp16(uB[s] + r0i * ROWB + c0i * 16, Bt + (size_t)(bn * 128 + r0i) * K + k0 + c0i * 8);
        cp16(uB[s] + r1i * ROWB + c1i * 16, Bt + (size_t)(bn * 128 + r1i) * K + k0 + c1i * 8);
    };

    loadTile(0, 0);
    asm volatile("cp.async.commit_group;");

    for (int i = 0; i < NC; i++) {
        const int s = i & 1;
        if (i + 1 < NC) {
            loadTile((i + 1) & 1, (i + 1) << 5);
            asm volatile("cp.async.commit_group;");
            asm volatile("cp.async.wait_group 1;");
        } else {
            asm volatile("cp.async.wait_group 0;");
        }
        __syncthreads();

        #pragma unroll
        for (int ks = 0; ks < 2; ks++) {
            uint32_t a[2][4];
            #pragma unroll
            for (int f = 0; f < 2; f++)
                ldm_x4(a[f][0], a[f][1], a[f][2], a[f][3],
                       uA[s] + (aRow + f * 16) * ROWB + ks * 32 + aColB);
            uint32_t b[8][2];
            #pragma unroll
            for (int p = 0; p < 4; p++) {
                uint32_t t0, t1, t2, t3;
                ldm_x4(t0, t1, t2, t3,
                       uB[s] + (bRow + p * 16) * ROWB + ks * 32 + bColB);
                b[2 * p][0] = t0; b[2 * p][1] = t1;
                b[2 * p + 1][0] = t2; b[2 * p + 1][1] = t3;
            }
            #pragma unroll
            for (int f = 0; f < 2; f++)
                #pragma unroll
                for (int q = 0; q < 8; q++)
                    mma16816(acc[f][q], a[f], b[q]);
        }
        __syncthreads();
    }

    // epilogue
    #pragma unroll
    for (int f = 0; f < 2; f++) {
        #pragma unroll
        for (int hrow = 0; hrow < 2; hrow++) {
            int row = bm * 128 + wm * 32 + f * 16 + (lid >> 2) + hrow * 8;
            if (row >= M) continue;
            #pragma unroll
            for (int q = 0; q < 8; q++) {
                int col = bn * 128 + wn * 64 + q * 8 + (lid & 3) * 2;
                float v0 = acc[f][q][hrow * 2 + 0];
                float v1 = acc[f][q][hrow * 2 + 1];
                if (EPI >= 1) { v0 += bias[col]; v1 += bias[col + 1]; }
                if (EPI == 1) {
                    float2 rr = *(const float2*)&res[(size_t)row * N + col];
                    v0 += rr.x; v1 += rr.y;
                }
                if (EPI == 2) {
                    v0 = gelu_exact(v0); v1 = gelu_exact(v1);
                    *(__half2*)&C16[(size_t)row * N + col] = __floats2half2_rn(v0, v1);
                } else {
                    float2 o; o.x = v0; o.y = v1;
                    *(float2*)&C[(size_t)row * N + col] = o;
                }
            }
        }
    }
}

// ---------------- Flash attention (causal), fp32 in, fp16 out ----------------
#define ATTN_SMEM ((4096 + 4096 + 64 * 65) * 4)

__global__ __launch_bounds__(128)
void attn_kernel(const float* __restrict__ Q, const float* __restrict__ K,
                 const float* __restrict__ V, __half* __restrict__ O) {
    extern __shared__ float sm[];
    float* Ks = sm;
    float* Vs = sm + 4096;
    float* Ps = sm + 8192;

    const int t    = threadIdx.x;
    const int r    = t >> 1;
    const int half = t & 1;
    const int iTile = blockIdx.x;
    const int bh = blockIdx.y;
    const int b = bh >> 4, h = bh & 15;
    const int qi = iTile * 64 + r;
    const bool qvalid = qi < SEQ;

    float4 q4[16];
    const float* qptr = Q + (size_t)(b * SEQ + (qvalid ? qi : 0)) * D_MODEL + h * 64;
    #pragma unroll
    for (int i = 0; i < 16; i++) q4[i] = ((const float4*)qptr)[i];

    float acc[32];
    #pragma unroll
    for (int i = 0; i < 32; i++) acc[i] = 0.f;
    float m = -INFINITY, l = 0.f;
    const float scale = 0.125f;

    for (int j = 0; j <= iTile; j++) {
        __syncthreads();
        #pragma unroll
        for (int it = 0; it < 8; it++) {
            int lin = it * 128 + t;
            int rr  = lin >> 4;
            int d4  = (lin & 15) << 2;
            int kj  = j * 64 + rr;
            float4 kv, vv;
            if (kj < SEQ) {
                size_t base = (size_t)(b * SEQ + kj) * D_MODEL + h * 64 + d4;
                kv = *(const float4*)(K + base);
                vv = *(const float4*)(V + base);
            } else {
                kv = make_float4(0.f, 0.f, 0.f, 0.f);
                vv = kv;
            }
            *(float4*)&Ks[rr * 64 + d4] = kv;
            *(float4*)&Vs[rr * 64 + d4] = vv;
        }
        __syncthreads();

        float s[32];
        #pragma unroll
        for (int cc = 0; cc < 32; cc++) {
            int c = half * 32 + cc;
            const float4* kr = (const float4*)&Ks[c * 64];
            float a0 = 0.f;
            #pragma unroll
            for (int d = 0; d < 16; d++) {
                float4 kk = kr[d];
                a0 += q4[d].x * kk.x + q4[d].y * kk.y + q4[d].z * kk.z + q4[d].w * kk.w;
            }
            int col = j * 64 + c;
            s[cc] = (col <= qi) ? a0 * scale : -INFINITY;
        }
        float tmax = -INFINITY;
        #pragma unroll
        for (int cc = 0; cc < 32; cc++) tmax = fmaxf(tmax, s[cc]);
        tmax = fmaxf(tmax, __shfl_xor_sync(0xffffffffu, tmax, 1));
        float mnew  = fmaxf(m, tmax);
        float alpha = __expf(m - mnew);
        float psum = 0.f;
        #pragma unroll
        for (int cc = 0; cc < 32; cc++) {
            float p = __expf(s[cc] - mnew);
            psum += p;
            Ps[r * 65 + half * 32 + cc] = p;
        }
        psum += __shfl_xor_sync(0xffffffffu, psum, 1);
        l = l * alpha + psum;
        m = mnew;
        __syncthreads();

        #pragma unroll
        for (int dd = 0; dd < 32; dd++) acc[dd] *= alpha;
        #pragma unroll 4
        for (int c = 0; c < 64; c++) {
            float p = Ps[r * 65 + c];
            const float4* vr = (const float4*)&Vs[c * 64 + half * 32];
            #pragma unroll
            for (int d8 = 0; d8 < 8; d8++) {
                float4 vv = vr[d8];
                acc[d8 * 4 + 0] += p * vv.x;
                acc[d8 * 4 + 1] += p * vv.y;
                acc[d8 * 4 + 2] += p * vv.z;
                acc[d8 * 4 + 3] += p * vv.w;
            }
        }
    }

    if (qvalid) {
        float inv = 1.f / l;
        __half2* op = (__half2*)(O + (size_t)(b * SEQ + qi) * D_MODEL + h * 64 + half * 32);
        #pragma unroll
        for (int d8 = 0; d8 < 8; d8++) {
            op[d8 * 2 + 0] = __floats2half2_rn(acc[d8 * 4 + 0] * inv, acc[d8 * 4 + 1] * inv);
            op[d8 * 2 + 1] = __floats2half2_rn(acc[d8 * 4 + 2] * inv, acc[d8 * 4 + 3] * inv);
        }
    }
}

// ---------------- launch ----------------
extern "C" void kernel_launch(void* const* d_in, const int* in_sizes, int n_in,
                              void* d_out, int out_size) {
    const float* x   = (const float*)d_in[0];
    const float* wq  = (const float*)d_in[1];
    const float* wk  = (const float*)d_in[2];
    const float* wv  = (const float*)d_in[3];
    const float* wo  = (const float*)d_in[4];
    const float* bo  = (const float*)d_in[5];
    const float* w1  = (const float*)d_in[6];
    const float* b1  = (const float*)d_in[7];
    const float* w2  = (const float*)d_in[8];
    const float* b2  = (const float*)d_in[9];
    const float* gg1 = (const float*)d_in[10];
    const float* be1 = (const float*)d_in[11];
    const float* gg2 = (const float*)d_in[12];
    const float* be2 = (const float*)d_in[13];
    float* out = (float*)d_out;

    float *pq, *pk, *pv, *px1;
    __half *pa16, *pb16, *pwq, *pwk, *pwv, *pwo, *pw1, *pw2;
    cudaGetSymbolAddress((void**)&pq,   g_q);
    cudaGetSymbolAddress((void**)&pk,   g_k);
    cudaGetSymbolAddress((void**)&pv,   g_v);
    cudaGetSymbolAddress((void**)&px1,  g_x1);
    cudaGetSymbolAddress((void**)&pa16, g_a16);
    cudaGetSymbolAddress((void**)&pb16, g_b16);
    cudaGetSymbolAddress((void**)&pwq,  g_wq16);
    cudaGetSymbolAddress((void**)&pwk,  g_wk16);
    cudaGetSymbolAddress((void**)&pwv,  g_wv16);
    cudaGetSymbolAddress((void**)&pwo,  g_wo16);
    cudaGetSymbolAddress((void**)&pw1,  g_w116);
    cudaGetSymbolAddress((void**)&pw2,  g_w216);

    cudaFuncSetAttribute(attn_kernel, cudaFuncAttributeMaxDynamicSharedMemorySize, ATTN_SMEM);

    dim3 wb(32, 8);
    wcvt_kernel<<<dim3(32, 32), wb>>>(wq, pwq, D_MODEL, D_MODEL);
    wcvt_kernel<<<dim3(32, 32), wb>>>(wk, pwk, D_MODEL, D_MODEL);
    wcvt_kernel<<<dim3(32, 32), wb>>>(wv, pwv, D_MODEL, D_MODEL);
    wcvt_kernel<<<dim3(32, 32), wb>>>(wo, pwo, D_MODEL, D_MODEL);
    wcvt_kernel<<<dim3(32, 128), wb>>>(w1, pw1, D_MODEL, D_FF);
    wcvt_kernel<<<dim3(128, 32), wb>>>(w2, pw2, D_FF, D_MODEL);

    dim3 gD(D_MODEL / 128, (M_ROWS + 127) / 128);   // (8, 63)
    dim3 gF(D_FF   / 128, (M_ROWS + 127) / 128);    // (32, 63)

    // 1. h16 = LN(x)
    ln16_kernel<<<M_ROWS, 256>>>(x, gg1, be1, pa16);
    // 2-4. Q,K,V (fp32 out for attention)
    mma_gemm<0><<<gD, 256>>>(pa16, pwq, pq, nullptr, M_ROWS, D_MODEL, D_MODEL, nullptr, nullptr);
    mma_gemm<0><<<gD, 256>>>(pa16, pwk, pk, nullptr, M_ROWS, D_MODEL, D_MODEL, nullptr, nullptr);
    mma_gemm<0><<<gD, 256>>>(pa16, pwv, pv, nullptr, M_ROWS, D_MODEL, D_MODEL, nullptr, nullptr);
    // 5. attention -> att16 (reuses a16; h16 dead after QKV)
    attn_kernel<<<dim3(16, BATCH * N_HEADS), 128, ATTN_SMEM>>>(pq, pk, pv, pa16);
    // 6. x1 = x + att @ Wo + bo
    mma_gemm<1><<<gD, 256>>>(pa16, pwo, px1, nullptr, M_ROWS, D_MODEL, D_MODEL, bo, x);
    // 7. h2_16 = LN(x1)
    ln16_kernel<<<M_ROWS, 256>>>(px1, gg2, be2, pa16);
    // 8. ff16 = gelu(h2 @ W1 + b1)
    mma_gemm<2><<<gF, 256>>>(pa16, pw1, nullptr, pb16, M_ROWS, D_FF, D_MODEL, b1, nullptr);
    // 9. out = x1 + ff @ W2 + b2
    mma_gemm<1><<<gD, 256>>>(pb16, pw2, out, nullptr, M_ROWS, D_MODEL, D_FF, b2, px1);
}

// round 4
// speedup vs baseline: 7.3112x; 2.2539x over previous
#include <cuda_runtime.h>
#include <cuda_fp16.h>
#include <math.h>
#include <stdint.h>

#define D_MODEL 1024
#define D_FF    4096
#define N_HEADS 16
#define SEQ     1000
#define BATCH   8
#define M_ROWS  (BATCH * SEQ)   // 8000

// ---------------- scratch (static device globals; no allocation) ----------------
__device__ float g_x1 [M_ROWS * D_MODEL];
__device__ __half g_qkv16[M_ROWS * 3 * D_MODEL];   // fused QKV output
__device__ __half g_a16[M_ROWS * D_MODEL];         // h16 / att16 / h2_16
__device__ __half g_b16[M_ROWS * D_FF];            // ff16
__device__ __half g_wqkv16[3 * D_MODEL * D_MODEL]; // [N=3072][K=1024]
__device__ __half g_wo16[D_MODEL * D_MODEL];
__device__ __half g_w116[D_FF * D_MODEL];          // [N=4096][K=1024]
__device__ __half g_w216[D_MODEL * D_FF];          // [N=1024][K=4096]

// ---------------- PTX helpers ----------------
__device__ __forceinline__ uint32_t smem_u32(const void* p) {
    uint32_t a;
    asm("{ .reg .u64 t; cvta.to.shared.u64 t, %1; cvt.u32.u64 %0, t; }" : "=r"(a) : "l"(p));
    return a;
}
__device__ __forceinline__ void cp16(uint32_t dst, const void* src) {
    asm volatile("cp.async.cg.shared.global [%0], [%1], 16;" :: "r"(dst), "l"(src));
}
__device__ __forceinline__ void ldm_x4(uint32_t& r0, uint32_t& r1, uint32_t& r2, uint32_t& r3,
                                       uint32_t addr) {
    asm volatile("ldmatrix.sync.aligned.m8n8.x4.shared.b16 {%0,%1,%2,%3}, [%4];"
                 : "=r"(r0), "=r"(r1), "=r"(r2), "=r"(r3) : "r"(addr));
}
__device__ __forceinline__ void ldm_x4t(uint32_t& r0, uint32_t& r1, uint32_t& r2, uint32_t& r3,
                                        uint32_t addr) {
    asm volatile("ldmatrix.sync.aligned.m8n8.x4.trans.shared.b16 {%0,%1,%2,%3}, [%4];"
                 : "=r"(r0), "=r"(r1), "=r"(r2), "=r"(r3) : "r"(addr));
}
__device__ __forceinline__ void mma16816(float* c, const uint32_t* a, const uint32_t* b) {
    asm volatile(
        "mma.sync.aligned.m16n8k16.row.col.f32.f16.f16.f32 "
        "{%0,%1,%2,%3}, {%4,%5,%6,%7}, {%8,%9}, {%0,%1,%2,%3};"
        : "+f"(c[0]), "+f"(c[1]), "+f"(c[2]), "+f"(c[3])
        : "r"(a[0]), "r"(a[1]), "r"(a[2]), "r"(a[3]), "r"(b[0]), "r"(b[1]));
}
__device__ __forceinline__ float gelu_exact(float x) {
    return 0.5f * x * (1.0f + erff(x * 0.70710678118654752f));
}
__device__ __forceinline__ uint32_t pk2(float a, float b) {
    __half2 h = __floats2half2_rn(a, b);
    return *(uint32_t*)&h;
}

// ---------------- LayerNorm -> fp16 out ----------------
__global__ void ln16_kernel(const float* __restrict__ x, const float* __restrict__ g,
                            const float* __restrict__ bt, __half* __restrict__ out) {
    int row = blockIdx.x;
    int t = threadIdx.x;
    const float4* xr = (const float4*)(x + (size_t)row * D_MODEL);
    float4 v = xr[t];
    float s  = v.x + v.y + v.z + v.w;
    float sq = v.x * v.x + v.y * v.y + v.z * v.z + v.w * v.w;
    #pragma unroll
    for (int o = 16; o > 0; o >>= 1) {
        s  += __shfl_xor_sync(0xffffffffu, s,  o);
        sq += __shfl_xor_sync(0xffffffffu, sq, o);
    }
    __shared__ float ss[8], ssq[8];
    int w = t >> 5;
    if ((t & 31) == 0) { ss[w] = s; ssq[w] = sq; }
    __syncthreads();
    float tot = 0.f, totq = 0.f;
    #pragma unroll
    for (int i = 0; i < 8; i++) { tot += ss[i]; totq += ssq[i]; }
    float mean = tot * (1.f / D_MODEL);
    float var  = totq * (1.f / D_MODEL) - mean * mean;
    float rstd = rsqrtf(var + 1e-5f);
    float4 gg = ((const float4*)g)[t];
    float4 bb = ((const float4*)bt)[t];
    float o0 = (v.x - mean) * rstd * gg.x + bb.x;
    float o1 = (v.y - mean) * rstd * gg.y + bb.y;
    float o2 = (v.z - mean) * rstd * gg.z + bb.z;
    float o3 = (v.w - mean) * rstd * gg.w + bb.w;
    __half2* op = (__half2*)(out + (size_t)row * D_MODEL);
    op[2 * t + 0] = __floats2half2_rn(o0, o1);
    op[2 * t + 1] = __floats2half2_rn(o2, o3);
}

// ---------------- weight transpose + convert: W[K,N] fp32 -> Wt[N,K] fp16 --------
__global__ void wcvt_kernel(const float* __restrict__ W, __half* __restrict__ Wt,
                            int K, int N) {
    __shared__ float t[32][33];
    int k0 = blockIdx.x * 32, n0 = blockIdx.y * 32;
    int tx = threadIdx.x, ty = threadIdx.y;     // (32, 8)
    #pragma unroll
    for (int r = 0; r < 32; r += 8)
        t[ty + r][tx] = W[(size_t)(k0 + ty + r) * N + n0 + tx];
    __syncthreads();
    #pragma unroll
    for (int r = 0; r < 32; r += 8)
        Wt[(size_t)(n0 + ty + r) * K + k0 + tx] = __float2half(t[tx][ty + r]);
}

// ---------------- fp16 tensor-core GEMM ------------------------------------------
// EPI: 0 plain fp32, 1 +bias+res fp32, 2 gelu(+bias) fp16, 3 plain fp16
#define ROWB 80

template<int EPI>
__global__ void __launch_bounds__(256, 2)
mma_gemm(const __half* __restrict__ A, const __half* __restrict__ Bt,
         float* __restrict__ C, __half* __restrict__ C16, int M, int N, int K,
         const float* __restrict__ bias, const float* __restrict__ res) {
    __shared__ __align__(128) char sA[2][128 * ROWB];
    __shared__ __align__(128) char sB[2][128 * ROWB];

    const int tid = threadIdx.x;
    const int lid = tid & 31;
    const int wid = tid >> 5;
    const int wm = wid & 3, wn = wid >> 2;
    const int bm = blockIdx.y, bn = blockIdx.x;

    uint32_t uA[2], uB[2];
    uA[0] = smem_u32(sA[0]); uA[1] = smem_u32(sA[1]);
    uB[0] = smem_u32(sB[0]); uB[1] = smem_u32(sB[1]);

    const int r0i = tid >> 2, c0i = tid & 3;
    const int r1i = (tid + 256) >> 2, c1i = tid & 3;

    const int part = lid >> 3;
    const int aRow  = wm * 32 + (part & 1) * 8 + (lid & 7);
    const int aColB = ((part >> 1) & 1) * 16;
    const int bRow  = wn * 64 + ((part >> 1) & 1) * 8 + (lid & 7);
    const int bColB = (part & 1) * 16;

    float acc[2][8][4];
    #pragma unroll
    for (int f = 0; f < 2; f++)
        #pragma unroll
        for (int q = 0; q < 8; q++)
            #pragma unroll
            for (int z = 0; z < 4; z++) acc[f][q][z] = 0.f;

    const int NC = K >> 5;

    auto loadTile = [&](int s, int k0) {
        int gr0 = bm * 128 + r0i; if (gr0 >= M) gr0 = M - 1;
        int gr1 = bm * 128 + r1i; if (gr1 >= M) gr1 = M - 1;
        cp16(uA[s] + r0i * ROWB + c0i * 16, A + (size_t)gr0 * K + k0 + c0i * 8);
        cp16(uA[s] + r1i * ROWB + c1i * 16, A + (size_t)gr1 * K + k0 + c1i * 8);
        cp16(uB[s] + r0i * ROWB + c0i * 16, Bt + (size_t)(bn * 128 + r0i) * K + k0 + c0i * 8);
        cp16(uB[s] + r1i * ROWB + c1i * 16, Bt + (size_t)(bn * 128 + r1i) * K + k0 + c1i * 8);
    };

    loadTile(0, 0);
    asm volatile("cp.async.commit_group;");

    for (int i = 0; i < NC; i++) {
        const int s = i & 1;
        if (i + 1 < NC) {
            loadTile((i + 1) & 1, (i + 1) << 5);
            asm volatile("cp.async.commit_group;");
            asm volatile("cp.async.wait_group 1;");
        } else {
            asm volatile("cp.async.wait_group 0;");
        }
        __syncthreads();

        #pragma unroll
        for (int ks = 0; ks < 2; ks++) {
            uint32_t a[2][4];
            #pragma unroll
            for (int f = 0; f < 2; f++)
                ldm_x4(a[f][0], a[f][1], a[f][2], a[f][3],
                       uA[s] + (aRow + f * 16) * ROWB + ks * 32 + aColB);
            uint32_t b[8][2];
            #pragma unroll
            for (int p = 0; p < 4; p++) {
                uint32_t t0, t1, t2, t3;
                ldm_x4(t0, t1, t2, t3,
                       uB[s] + (bRow + p * 16) * ROWB + ks * 32 + bColB);
                b[2 * p][0] = t0; b[2 * p][1] = t1;
                b[2 * p + 1][0] = t2; b[2 * p + 1][1] = t3;
            }
            #pragma unroll
            for (int f = 0; f < 2; f++)
                #pragma unroll
                for (int q = 0; q < 8; q++)
                    mma16816(acc[f][q], a[f], b[q]);
        }
        __syncthreads();
    }

    #pragma unroll
    for (int f = 0; f < 2; f++) {
        #pragma unroll
        for (int hrow = 0; hrow < 2; hrow++) {
            int row = bm * 128 + wm * 32 + f * 16 + (lid >> 2) + hrow * 8;
            if (row >= M) continue;
            #pragma unroll
            for (int q = 0; q < 8; q++) {
                int col = bn * 128 + wn * 64 + q * 8 + (lid & 3) * 2;
                float v0 = acc[f][q][hrow * 2 + 0];
                float v1 = acc[f][q][hrow * 2 + 1];
                if (EPI == 1 || EPI == 2) { v0 += bias[col]; v1 += bias[col + 1]; }
                if (EPI == 1) {
                    float2 rr = *(const float2*)&res[(size_t)row * N + col];
                    v0 += rr.x; v1 += rr.y;
                }
                if (EPI == 2) {
                    v0 = gelu_exact(v0); v1 = gelu_exact(v1);
                    *(__half2*)&C16[(size_t)row * N + col] = __floats2half2_rn(v0, v1);
                } else if (EPI == 3) {
                    *(__half2*)&C16[(size_t)row * N + col] = __floats2half2_rn(v0, v1);
                } else {
                    float2 o; o.x = v0; o.y = v1;
                    *(float2*)&C[(size_t)row * N + col] = o;
                }
            }
        }
    }
}

// ---------------- Tensor-core flash attention (causal) ---------------------------
// fp16 QKV in (packed [M, 3072]), fp16 out (att [M, 1024]).
// 64 q-rows/block, 4 warps (each 16 q-rows), 64-key tiles, cp.async double buffer.
#define AT_ROWB 144
#define QKVSTR (3 * D_MODEL)

__global__ void __launch_bounds__(128, 2)
attn16_kernel(const __half* __restrict__ QKV, __half* __restrict__ O) {
    __shared__ __align__(128) char sK[2][64 * AT_ROWB];
    __shared__ __align__(128) char sV[2][64 * AT_ROWB];
    __shared__ __align__(128) char sQ[64 * AT_ROWB];

    const int tid = threadIdx.x;
    const int lid = tid & 31;
    const int wid = tid >> 5;
    const int iTile = blockIdx.x;
    const int bh = blockIdx.y;
    const int b = bh >> 4, h = bh & 15;

    uint32_t uK[2], uV[2], uQ;
    uK[0] = smem_u32(sK[0]); uK[1] = smem_u32(sK[1]);
    uV[0] = smem_u32(sV[0]); uV[1] = smem_u32(sV[1]);
    uQ = smem_u32(sQ);

    const __half* Qg = QKV + h * 64;
    const __half* Kg = QKV + D_MODEL + h * 64;
    const __half* Vg = QKV + 2 * D_MODEL + h * 64;

    // Q tile -> smem (regular loads)
    #pragma unroll
    for (int i = 0; i < 4; i++) {
        int lin = i * 128 + tid;
        int rr = lin >> 3, cb = (lin & 7) * 16;
        int qi = iTile * 64 + rr; if (qi >= SEQ) qi = SEQ - 1;
        *(uint4*)(sQ + rr * AT_ROWB + cb) =
            *(const uint4*)((const char*)(Qg + (size_t)(b * SEQ + qi) * QKVSTR) + cb);
    }

    auto loadKV = [&](int s, int j) {
        #pragma unroll
        for (int i = 0; i < 4; i++) {
            int lin = i * 128 + tid;
            int rr = lin >> 3, cb = (lin & 7) * 16;
            int kj = j * 64 + rr; if (kj >= SEQ) kj = SEQ - 1;
            size_t rowoff = (size_t)(b * SEQ + kj) * QKVSTR;
            cp16(uK[s] + rr * AT_ROWB + cb, (const char*)(Kg + rowoff) + cb);
            cp16(uV[s] + rr * AT_ROWB + cb, (const char*)(Vg + rowoff) + cb);
        }
    };

    loadKV(0, 0);
    asm volatile("cp.async.commit_group;");
    __syncthreads();   // sQ visible

    // Q fragments (A, m16k16 x4)
    const int part = lid >> 3;
    const int aRow  = wid * 16 + (part & 1) * 8 + (lid & 7);
    const int aColB = ((part >> 1) & 1) * 16;
    uint32_t qf[4][4];
    #pragma unroll
    for (int kt = 0; kt < 4; kt++)
        ldm_x4(qf[kt][0], qf[kt][1], qf[kt][2], qf[kt][3],
               uQ + aRow * AT_ROWB + kt * 32 + aColB);

    float o[8][4];
    #pragma unroll
    for (int q = 0; q < 8; q++)
        #pragma unroll
        for (int z = 0; z < 4; z++) o[q][z] = 0.f;
    float m0 = -1e30f, m1 = -1e30f, l0 = 0.f, l1 = 0.f;

    const int rowg0 = iTile * 64 + wid * 16 + (lid >> 2);
    const int rowg1 = rowg0 + 8;
    const float scale = 0.125f;

    const int kbRow  = ((part >> 1) & 1) * 8 + (lid & 7);
    const int kbColB = (part & 1) * 16;
    const int vRow   = (part & 1) * 8 + (lid & 7);
    const int vColB  = ((part >> 1) & 1) * 16;

    for (int j = 0; j <= iTile; j++) {
        const int s = j & 1;
        if (j < iTile) {
            loadKV((j + 1) & 1, j + 1);
            asm volatile("cp.async.commit_group;");
            asm volatile("cp.async.wait_group 1;");
        } else {
            asm volatile("cp.async.wait_group 0;");
        }
        __syncthreads();

        // S = Q @ K^T  (fp32 acc)
        float c[8][4];
        #pragma unroll
        for (int q = 0; q < 8; q++)
            #pragma unroll
            for (int z = 0; z < 4; z++) c[q][z] = 0.f;
        #pragma unroll
        for (int kt = 0; kt < 4; kt++) {
            uint32_t bfr[8][2];
            #pragma unroll
            for (int ng = 0; ng < 4; ng++) {
                uint32_t t0, t1, t2, t3;
                ldm_x4(t0, t1, t2, t3,
                       uK[s] + (ng * 16 + kbRow) * AT_ROWB + kt * 32 + kbColB);
                bfr[2 * ng][0] = t0; bfr[2 * ng][1] = t1;
                bfr[2 * ng + 1][0] = t2; bfr[2 * ng + 1][1] = t3;
            }
            #pragma unroll
            for (int q = 0; q < 8; q++)
                mma16816(c[q], qf[kt], bfr[q]);
        }

        // scale (+ causal mask on diagonal tile)
        if (j == iTile) {
            #pragma unroll
            for (int q = 0; q < 8; q++) {
                int colg = j * 64 + q * 8 + (lid & 3) * 2;
                c[q][0] = (colg     <= rowg0) ? c[q][0] * scale : -1e30f;
                c[q][1] = (colg + 1 <= rowg0) ? c[q][1] * scale : -1e30f;
                c[q][2] = (colg     <= rowg1) ? c[q][2] * scale : -1e30f;
                c[q][3] = (colg + 1 <= rowg1) ? c[q][3] * scale : -1e30f;
            }
        } else {
            #pragma unroll
            for (int q = 0; q < 8; q++) {
                c[q][0] *= scale; c[q][1] *= scale;
                c[q][2] *= scale; c[q][3] *= scale;
            }
        }

        // online softmax
        float mx0 = -1e30f, mx1 = -1e30f;
        #pragma unroll
        for (int q = 0; q < 8; q++) {
            mx0 = fmaxf(mx0, fmaxf(c[q][0], c[q][1]));
            mx1 = fmaxf(mx1, fmaxf(c[q][2], c[q][3]));
        }
        mx0 = fmaxf(mx0, __shfl_xor_sync(0xffffffffu, mx0, 1));
        mx0 = fmaxf(mx0, __shfl_xor_sync(0xffffffffu, mx0, 2));
        mx1 = fmaxf(mx1, __shfl_xor_sync(0xffffffffu, mx1, 1));
        mx1 = fmaxf(mx1, __shfl_xor_sync(0xffffffffu, mx1, 2));
        float mn0 = fmaxf(m0, mx0), mn1 = fmaxf(m1, mx1);
        float a0 = __expf(m0 - mn0), a1 = __expf(m1 - mn1);
        float s0 = 0.f, s1 = 0.f;
        #pragma unroll
        for (int q = 0; q < 8; q++) {
            c[q][0] = __expf(c[q][0] - mn0); s0 += c[q][0];
            c[q][1] = __expf(c[q][1] - mn0); s0 += c[q][1];
            c[q][2] = __expf(c[q][2] - mn1); s1 += c[q][2];
            c[q][3] = __expf(c[q][3] - mn1); s1 += c[q][3];
        }
        s0 += __shfl_xor_sync(0xffffffffu, s0, 1);
        s0 += __shfl_xor_sync(0xffffffffu, s0, 2);
        s1 += __shfl_xor_sync(0xffffffffu, s1, 1);
        s1 += __shfl_xor_sync(0xffffffffu, s1, 2);
        l0 = l0 * a0 + s0;
        l1 = l1 * a1 + s1;
        m0 = mn0; m1 = mn1;

        // pack P -> A fragments
        uint32_t pa[4][4];
        #pragma unroll
        for (int kt = 0; kt < 4; kt++) {
            pa[kt][0] = pk2(c[2 * kt][0],     c[2 * kt][1]);
            pa[kt][1] = pk2(c[2 * kt][2],     c[2 * kt][3]);
            pa[kt][2] = pk2(c[2 * kt + 1][0], c[2 * kt + 1][1]);
            pa[kt][3] = pk2(c[2 * kt + 1][2], c[2 * kt + 1][3]);
        }

        // O = O*alpha + P @ V
        #pragma unroll
        for (int q = 0; q < 8; q++) {
            o[q][0] *= a0; o[q][1] *= a0;
            o[q][2] *= a1; o[q][3] *= a1;
        }
        #pragma unroll
        for (int kt = 0; kt < 4; kt++) {
            uint32_t vfr[8][2];
            #pragma unroll
            for (int ng = 0; ng < 4; ng++) {
                uint32_t t0, t1, t2, t3;
                ldm_x4t(t0, t1, t2, t3,
                        uV[s] + (kt * 16 + vRow) * AT_ROWB + ng * 32 + vColB);
                vfr[2 * ng][0] = t0; vfr[2 * ng][1] = t1;
                vfr[2 * ng + 1][0] = t2; vfr[2 * ng + 1][1] = t3;
            }
            #pragma unroll
            for (int q = 0; q < 8; q++)
                mma16816(o[q], pa[kt], vfr[q]);
        }
        __syncthreads();
    }

    // store
    float inv0 = 1.f / l0, inv1 = 1.f / l1;
    #pragma unroll
    for (int q = 0; q < 8; q++) {
        int col = h * 64 + q * 8 + (lid & 3) * 2;
        if (rowg0 < SEQ)
            *(__half2*)&O[(size_t)(b * SEQ + rowg0) * D_MODEL + col] =
                __floats2half2_rn(o[q][0] * inv0, o[q][1] * inv0);
        if (rowg1 < SEQ)
            *(__half2*)&O[(size_t)(b * SEQ + rowg1) * D_MODEL + col] =
                __floats2half2_rn(o[q][2] * inv1, o[q][3] * inv1);
    }
}

// ---------------- launch ----------------
extern "C" void kernel_launch(void* const* d_in, const int* in_sizes, int n_in,
                              void* d_out, int out_size) {
    const float* x   = (const float*)d_in[0];
    const float* wq  = (const float*)d_in[1];
    const float* wk  = (const float*)d_in[2];
    const float* wv  = (const float*)d_in[3];
    const float* wo  = (const float*)d_in[4];
    const float* bo  = (const float*)d_in[5];
    const float* w1  = (const float*)d_in[6];
    const float* b1  = (const float*)d_in[7];
    const float* w2  = (const float*)d_in[8];
    const float* b2  = (const float*)d_in[9];
    const float* gg1 = (const float*)d_in[10];
    const float* be1 = (const float*)d_in[11];
    const float* gg2 = (const float*)d_in[12];
    const float* be2 = (const float*)d_in[13];
    float* out = (float*)d_out;

    float *px1;
    __half *pqkv, *pa16, *pb16, *pwqkv, *pwo, *pw1, *pw2;
    cudaGetSymbolAddress((void**)&px1,   g_x1);
    cudaGetSymbolAddress((void**)&pqkv,  g_qkv16);
    cudaGetSymbolAddress((void**)&pa16,  g_a16);
    cudaGetSymbolAddress((void**)&pb16,  g_b16);
    cudaGetSymbolAddress((void**)&pwqkv, g_wqkv16);
    cudaGetSymbolAddress((void**)&pwo,   g_wo16);
    cudaGetSymbolAddress((void**)&pw1,   g_w116);
    cudaGetSymbolAddress((void**)&pw2,   g_w216);

    dim3 wb(32, 8);
    // concat QKV weight: rows [0,1024)=Wq, [1024,2048)=Wk, [2048,3072)=Wv
    wcvt_kernel<<<dim3(32, 32), wb>>>(wq, pwqkv,                       D_MODEL, D_MODEL);
    wcvt_kernel<<<dim3(32, 32), wb>>>(wk, pwqkv + 1024 * 1024,        D_MODEL, D_MODEL);
    wcvt_kernel<<<dim3(32, 32), wb>>>(wv, pwqkv + 2 * 1024 * 1024,    D_MODEL, D_MODEL);
    wcvt_kernel<<<dim3(32, 32), wb>>>(wo, pwo, D_MODEL, D_MODEL);
    wcvt_kernel<<<dim3(32, 128), wb>>>(w1, pw1, D_MODEL, D_FF);
    wcvt_kernel<<<dim3(128, 32), wb>>>(w2, pw2, D_FF, D_MODEL);

    dim3 gQKV(3 * D_MODEL / 128, (M_ROWS + 127) / 128);  // (24, 63)
    dim3 gD(D_MODEL / 128, (M_ROWS + 127) / 128);        // (8, 63)
    dim3 gF(D_FF / 128, (M_ROWS + 127) / 128);           // (32, 63)

    // 1. h16 = LN(x)
    ln16_kernel<<<M_ROWS, 256>>>(x, gg1, be1, pa16);
    // 2. QKV = h @ [Wq|Wk|Wv]  (fp16 out)
    mma_gemm<3><<<gQKV, 256>>>(pa16, pwqkv, nullptr, pqkv, M_ROWS, 3 * D_MODEL, D_MODEL, nullptr, nullptr);
    // 3. tensor-core flash attention -> att16
    attn16_kernel<<<dim3(16, BATCH * N_HEADS), 128>>>(pqkv, pa16);
    // 4. x1 = x + att @ Wo + bo
    mma_gemm<1><<<gD, 256>>>(pa16, pwo, px1, nullptr, M_ROWS, D_MODEL, D_MODEL, bo, x);
    // 5. h2_16 = LN(x1)
    ln16_kernel<<<M_ROWS, 256>>>(px1, gg2, be2, pa16);
    // 6. ff16 = gelu(h2 @ W1 + b1)
    mma_gemm<2><<<gF, 256>>>(pa16, pw1, nullptr, pb16, M_ROWS, D_FF, D_MODEL, b1, nullptr);
    // 7. out = x1 + ff @ W2 + b2
    mma_gemm<1><<<gD, 256>>>(pb16, pw2, out, nullptr, M_ROWS, D_MODEL, D_FF, b2, px1);
}

// round 5
// speedup vs baseline: 7.6598x; 1.0477x over previous
#include <cuda_runtime.h>
#include <cuda_fp16.h>
#include <math.h>
#include <stdint.h>

#define D_MODEL 1024
#define D_FF    4096
#define N_HEADS 16
#define SEQ     1000
#define BATCH   8
#define M_ROWS  (BATCH * SEQ)   // 8000

// ---------------- scratch (static device globals; no allocation) ----------------
__device__ float g_x1 [M_ROWS * D_MODEL];
__device__ __half g_qkv16[M_ROWS * 3 * D_MODEL];
__device__ __half g_a16[M_ROWS * D_MODEL];
__device__ __half g_b16[M_ROWS * D_FF];
__device__ __half g_wqkv16[3 * D_MODEL * D_MODEL];
__device__ __half g_wo16[D_MODEL * D_MODEL];
__device__ __half g_w116[D_FF * D_MODEL];
__device__ __half g_w216[D_MODEL * D_FF];

// ---------------- PTX helpers ----------------
__device__ __forceinline__ uint32_t smem_u32(const void* p) {
    uint32_t a;
    asm("{ .reg .u64 t; cvta.to.shared.u64 t, %1; cvt.u32.u64 %0, t; }" : "=r"(a) : "l"(p));
    return a;
}
__device__ __forceinline__ void cp16(uint32_t dst, const void* src) {
    asm volatile("cp.async.cg.shared.global [%0], [%1], 16;" :: "r"(dst), "l"(src));
}
__device__ __forceinline__ void ldm_x4(uint32_t& r0, uint32_t& r1, uint32_t& r2, uint32_t& r3,
                                       uint32_t addr) {
    asm volatile("ldmatrix.sync.aligned.m8n8.x4.shared.b16 {%0,%1,%2,%3}, [%4];"
                 : "=r"(r0), "=r"(r1), "=r"(r2), "=r"(r3) : "r"(addr));
}
__device__ __forceinline__ void ldm_x4t(uint32_t& r0, uint32_t& r1, uint32_t& r2, uint32_t& r3,
                                        uint32_t addr) {
    asm volatile("ldmatrix.sync.aligned.m8n8.x4.trans.shared.b16 {%0,%1,%2,%3}, [%4];"
                 : "=r"(r0), "=r"(r1), "=r"(r2), "=r"(r3) : "r"(addr));
}
__device__ __forceinline__ void mma16816(float* c, const uint32_t* a, const uint32_t* b) {
    asm volatile(
        "mma.sync.aligned.m16n8k16.row.col.f32.f16.f16.f32 "
        "{%0,%1,%2,%3}, {%4,%5,%6,%7}, {%8,%9}, {%0,%1,%2,%3};"
        : "+f"(c[0]), "+f"(c[1]), "+f"(c[2]), "+f"(c[3])
        : "r"(a[0]), "r"(a[1]), "r"(a[2]), "r"(a[3]), "r"(b[0]), "r"(b[1]));
}
__device__ __forceinline__ float gelu_exact(float x) {
    return 0.5f * x * (1.0f + erff(x * 0.70710678118654752f));
}
__device__ __forceinline__ uint32_t pk2(float a, float b) {
    __half2 h = __floats2half2_rn(a, b);
    return *(uint32_t*)&h;
}

// ---------------- LayerNorm -> fp16 out ----------------
__global__ void ln16_kernel(const float* __restrict__ x, const float* __restrict__ g,
                            const float* __restrict__ bt, __half* __restrict__ out) {
    int row = blockIdx.x;
    int t = threadIdx.x;
    const float4* xr = (const float4*)(x + (size_t)row * D_MODEL);
    float4 v = xr[t];
    float s  = v.x + v.y + v.z + v.w;
    float sq = v.x * v.x + v.y * v.y + v.z * v.z + v.w * v.w;
    #pragma unroll
    for (int o = 16; o > 0; o >>= 1) {
        s  += __shfl_xor_sync(0xffffffffu, s,  o);
        sq += __shfl_xor_sync(0xffffffffu, sq, o);
    }
    __shared__ float ss[8], ssq[8];
    int w = t >> 5;
    if ((t & 31) == 0) { ss[w] = s; ssq[w] = sq; }
    __syncthreads();
    float tot = 0.f, totq = 0.f;
    #pragma unroll
    for (int i = 0; i < 8; i++) { tot += ss[i]; totq += ssq[i]; }
    float mean = tot * (1.f / D_MODEL);
    float var  = totq * (1.f / D_MODEL) - mean * mean;
    float rstd = rsqrtf(var + 1e-5f);
    float4 gg = ((const float4*)g)[t];
    float4 bb = ((const float4*)bt)[t];
    float o0 = (v.x - mean) * rstd * gg.x + bb.x;
    float o1 = (v.y - mean) * rstd * gg.y + bb.y;
    float o2 = (v.z - mean) * rstd * gg.z + bb.z;
    float o3 = (v.w - mean) * rstd * gg.w + bb.w;
    __half2* op = (__half2*)(out + (size_t)row * D_MODEL);
    op[2 * t + 0] = __floats2half2_rn(o0, o1);
    op[2 * t + 1] = __floats2half2_rn(o2, o3);
}

// ---------------- fused weight transpose+convert (one launch, 6 weights) --------
__device__ __forceinline__ void wcvt_tile(const float* __restrict__ W, __half* __restrict__ Wt,
                                          int K, int N, int kb, int nb,
                                          int tx, int ty, float (*t)[33]) {
    int k0 = kb * 32, n0 = nb * 32;
    #pragma unroll
    for (int r = 0; r < 32; r += 8)
        t[ty + r][tx] = W[(size_t)(k0 + ty + r) * N + n0 + tx];
    __syncthreads();
    #pragma unroll
    for (int r = 0; r < 32; r += 8)
        Wt[(size_t)(n0 + ty + r) * K + k0 + tx] = __float2half(t[tx][ty + r]);
}

__global__ void wcvt_all(const float* wq, const float* wk, const float* wv,
                         const float* wo, const float* w1, const float* w2,
                         __half* dqkv, __half* dwo, __half* dw1, __half* dw2) {
    __shared__ float t[32][33];
    int blk = blockIdx.x;
    int tx = threadIdx.x, ty = threadIdx.y;
    if (blk < 4096) {
        const float* src = (blk < 1024) ? wq : (blk < 2048) ? wk : (blk < 3072) ? wv : wo;
        __half* dst = (blk < 3072) ? (dqkv + (size_t)(blk >> 10) * 1024 * 1024) : dwo;
        int local = blk & 1023;
        wcvt_tile(src, dst, 1024, 1024, local & 31, local >> 5, tx, ty, t);
    } else if (blk < 8192) {
        int local = blk - 4096;   // w1: K=1024, N=4096, grid 32 x 128
        wcvt_tile(w1, dw1, 1024, 4096, local & 31, local >> 5, tx, ty, t);
    } else {
        int local = blk - 8192;   // w2: K=4096, N=1024, grid 128 x 32
        wcvt_tile(w2, dw2, 4096, 1024, local & 127, local >> 7, tx, ty, t);
    }
}

// ---------------- fp16 tensor-core GEMM (3-stage cp.async, 1 sync/iter) ----------
// EPI: 0 plain fp32, 1 +bias+res fp32, 2 gelu(+bias) fp16, 3 plain fp16
#define ROWB 80
#define STAGE_B (128 * ROWB)            // 10240
#define GEMM_SMEM (6 * STAGE_B)         // 61440

template<int EPI>
__global__ void __launch_bounds__(256, 2)
mma_gemm(const __half* __restrict__ A, const __half* __restrict__ Bt,
         float* __restrict__ C, __half* __restrict__ C16, int M, int N, int K,
         const float* __restrict__ bias, const float* __restrict__ res) {
    extern __shared__ __align__(128) char smem[];
    const uint32_t base = smem_u32(smem);

    const int tid = threadIdx.x;
    const int lid = tid & 31;
    const int wid = tid >> 5;
    const int wm = wid & 3, wn = wid >> 2;
    const int bm = blockIdx.y, bn = blockIdx.x;

    const int r0i = tid >> 2, c0i = tid & 3;
    const int r1i = (tid + 256) >> 2;

    const int part = lid >> 3;
    const int aRow  = wm * 32 + (part & 1) * 8 + (lid & 7);
    const int aColB = ((part >> 1) & 1) * 16;
    const int bRow  = wn * 64 + ((part >> 1) & 1) * 8 + (lid & 7);
    const int bColB = (part & 1) * 16;

    float acc[2][8][4];
    #pragma unroll
    for (int f = 0; f < 2; f++)
        #pragma unroll
        for (int q = 0; q < 8; q++)
            #pragma unroll
            for (int z = 0; z < 4; z++) acc[f][q][z] = 0.f;

    const int NC = K >> 5;

    auto uAs = [&](int s) { return base + s * STAGE_B; };
    auto uBs = [&](int s) { return base + 3 * STAGE_B + s * STAGE_B; };

    auto loadTile = [&](int s, int k0) {
        int gr0 = bm * 128 + r0i; if (gr0 >= M) gr0 = M - 1;
        int gr1 = bm * 128 + r1i; if (gr1 >= M) gr1 = M - 1;
        cp16(uAs(s) + r0i * ROWB + c0i * 16, A + (size_t)gr0 * K + k0 + c0i * 8);
        cp16(uAs(s) + r1i * ROWB + c0i * 16, A + (size_t)gr1 * K + k0 + c0i * 8);
        cp16(uBs(s) + r0i * ROWB + c0i * 16, Bt + (size_t)(bn * 128 + r0i) * K + k0 + c0i * 8);
        cp16(uBs(s) + r1i * ROWB + c0i * 16, Bt + (size_t)(bn * 128 + r1i) * K + k0 + c0i * 8);
    };

    loadTile(0, 0);
    asm volatile("cp.async.commit_group;");
    loadTile(1, 32);
    asm volatile("cp.async.commit_group;");

    int s = 0;
    for (int i = 0; i < NC; i++) {
        if (i + 1 < NC) asm volatile("cp.async.wait_group 1;");
        else            asm volatile("cp.async.wait_group 0;");
        __syncthreads();
        if (i + 2 < NC) {
            int s2 = s + 2; if (s2 >= 3) s2 -= 3;
            loadTile(s2, (i + 2) << 5);
            asm volatile("cp.async.commit_group;");
        }

        const uint32_t ua = uAs(s), ub = uBs(s);
        #pragma unroll
        for (int ks = 0; ks < 2; ks++) {
            uint32_t a[2][4];
            #pragma unroll
            for (int f = 0; f < 2; f++)
                ldm_x4(a[f][0], a[f][1], a[f][2], a[f][3],
                       ua + (aRow + f * 16) * ROWB + ks * 32 + aColB);
            uint32_t b[8][2];
            #pragma unroll
            for (int p = 0; p < 4; p++) {
                uint32_t t0, t1, t2, t3;
                ldm_x4(t0, t1, t2, t3,
                       ub + (bRow + p * 16) * ROWB + ks * 32 + bColB);
                b[2 * p][0] = t0; b[2 * p][1] = t1;
                b[2 * p + 1][0] = t2; b[2 * p + 1][1] = t3;
            }
            #pragma unroll
            for (int f = 0; f < 2; f++)
                #pragma unroll
                for (int q = 0; q < 8; q++)
                    mma16816(acc[f][q], a[f], b[q]);
        }
        if (++s >= 3) s = 0;
    }

    #pragma unroll
    for (int f = 0; f < 2; f++) {
        #pragma unroll
        for (int hrow = 0; hrow < 2; hrow++) {
            int row = bm * 128 + wm * 32 + f * 16 + (lid >> 2) + hrow * 8;
            if (row >= M) continue;
            #pragma unroll
            for (int q = 0; q < 8; q++) {
                int col = bn * 128 + wn * 64 + q * 8 + (lid & 3) * 2;
                float v0 = acc[f][q][hrow * 2 + 0];
                float v1 = acc[f][q][hrow * 2 + 1];
                if (EPI == 1 || EPI == 2) { v0 += bias[col]; v1 += bias[col + 1]; }
                if (EPI == 1) {
                    float2 rr = *(const float2*)&res[(size_t)row * N + col];
                    v0 += rr.x; v1 += rr.y;
                }
                if (EPI == 2) {
                    v0 = gelu_exact(v0); v1 = gelu_exact(v1);
                    *(__half2*)&C16[(size_t)row * N + col] = __floats2half2_rn(v0, v1);
                } else if (EPI == 3) {
                    *(__half2*)&C16[(size_t)row * N + col] = __floats2half2_rn(v0, v1);
                } else {
                    float2 o; o.x = v0; o.y = v1;
                    *(float2*)&C[(size_t)row * N + col] = o;
                }
            }
        }
    }
}

// ---------------- Tensor-core flash attention (causal) ---------------------------
#define AT_ROWB 144
#define QKVSTR (3 * D_MODEL)

__global__ void __launch_bounds__(128, 2)
attn16_kernel(const __half* __restrict__ QKV, __half* __restrict__ O) {
    __shared__ __align__(128) char sK[2][64 * AT_ROWB];
    __shared__ __align__(128) char sV[2][64 * AT_ROWB];
    __shared__ __align__(128) char sQ[64 * AT_ROWB];

    const int tid = threadIdx.x;
    const int lid = tid & 31;
    const int wid = tid >> 5;
    const int iTile = blockIdx.x;
    const int bh = blockIdx.y;
    const int b = bh >> 4, h = bh & 15;

    uint32_t uK[2], uV[2], uQ;
    uK[0] = smem_u32(sK[0]); uK[1] = smem_u32(sK[1]);
    uV[0] = smem_u32(sV[0]); uV[1] = smem_u32(sV[1]);
    uQ = smem_u32(sQ);

    const __half* Qg = QKV + h * 64;
    const __half* Kg = QKV + D_MODEL + h * 64;
    const __half* Vg = QKV + 2 * D_MODEL + h * 64;

    #pragma unroll
    for (int i = 0; i < 4; i++) {
        int lin = i * 128 + tid;
        int rr = lin >> 3, cb = (lin & 7) * 16;
        int qi = iTile * 64 + rr; if (qi >= SEQ) qi = SEQ - 1;
        *(uint4*)(sQ + rr * AT_ROWB + cb) =
            *(const uint4*)((const char*)(Qg + (size_t)(b * SEQ + qi) * QKVSTR) + cb);
    }

    auto loadKV = [&](int s, int j) {
        #pragma unroll
        for (int i = 0; i < 4; i++) {
            int lin = i * 128 + tid;
            int rr = lin >> 3, cb = (lin & 7) * 16;
            int kj = j * 64 + rr; if (kj >= SEQ) kj = SEQ - 1;
            size_t rowoff = (size_t)(b * SEQ + kj) * QKVSTR;
            cp16(uK[s] + rr * AT_ROWB + cb, (const char*)(Kg + rowoff) + cb);
            cp16(uV[s] + rr * AT_ROWB + cb, (const char*)(Vg + rowoff) + cb);
        }
    };

    loadKV(0, 0);
    asm volatile("cp.async.commit_group;");
    __syncthreads();   // sQ visible

    const int part = lid >> 3;
    const int aRow  = wid * 16 + (part & 1) * 8 + (lid & 7);
    const int aColB = ((part >> 1) & 1) * 16;
    uint32_t qf[4][4];
    #pragma unroll
    for (int kt = 0; kt < 4; kt++)
        ldm_x4(qf[kt][0], qf[kt][1], qf[kt][2], qf[kt][3],
               uQ + aRow * AT_ROWB + kt * 32 + aColB);

    float o[8][4];
    #pragma unroll
    for (int q = 0; q < 8; q++)
        #pragma unroll
        for (int z = 0; z < 4; z++) o[q][z] = 0.f;
    float m0 = -1e30f, m1 = -1e30f, l0 = 0.f, l1 = 0.f;

    const int rowg0 = iTile * 64 + wid * 16 + (lid >> 2);
    const int rowg1 = rowg0 + 8;
    const float scale = 0.125f;

    const int kbRow  = ((part >> 1) & 1) * 8 + (lid & 7);
    const int kbColB = (part & 1) * 16;
    const int vRow   = (part & 1) * 8 + (lid & 7);
    const int vColB  = ((part >> 1) & 1) * 16;

    for (int j = 0; j <= iTile; j++) {
        const int s = j & 1;
        asm volatile("cp.async.wait_group 0;");
        __syncthreads();
        if (j < iTile) {
            loadKV(s ^ 1, j + 1);
            asm volatile("cp.async.commit_group;");
        }

        float c[8][4];
        #pragma unroll
        for (int q = 0; q < 8; q++)
            #pragma unroll
            for (int z = 0; z < 4; z++) c[q][z] = 0.f;
        #pragma unroll
        for (int kt = 0; kt < 4; kt++) {
            uint32_t bfr[8][2];
            #pragma unroll
            for (int ng = 0; ng < 4; ng++) {
                uint32_t t0, t1, t2, t3;
                ldm_x4(t0, t1, t2, t3,
                       uK[s] + (ng * 16 + kbRow) * AT_ROWB + kt * 32 + kbColB);
                bfr[2 * ng][0] = t0; bfr[2 * ng][1] = t1;
                bfr[2 * ng + 1][0] = t2; bfr[2 * ng + 1][1] = t3;
            }
            #pragma unroll
            for (int q = 0; q < 8; q++)
                mma16816(c[q], qf[kt], bfr[q]);
        }

        if (j == iTile) {
            #pragma unroll
            for (int q = 0; q < 8; q++) {
                int colg = j * 64 + q * 8 + (lid & 3) * 2;
                c[q][0] = (colg     <= rowg0) ? c[q][0] * scale : -1e30f;
                c[q][1] = (colg + 1 <= rowg0) ? c[q][1] * scale : -1e30f;
                c[q][2] = (colg     <= rowg1) ? c[q][2] * scale : -1e30f;
                c[q][3] = (colg + 1 <= rowg1) ? c[q][3] * scale : -1e30f;
            }
        } else {
            #pragma unroll
            for (int q = 0; q < 8; q++) {
                c[q][0] *= scale; c[q][1] *= scale;
                c[q][2] *= scale; c[q][3] *= scale;
            }
        }

        float mx0 = -1e30f, mx1 = -1e30f;
        #pragma unroll
        for (int q = 0; q < 8; q++) {
            mx0 = fmaxf(mx0, fmaxf(c[q][0], c[q][1]));
            mx1 = fmaxf(mx1, fmaxf(c[q][2], c[q][3]));
        }
        mx0 = fmaxf(mx0, __shfl_xor_sync(0xffffffffu, mx0, 1));
        mx0 = fmaxf(mx0, __shfl_xor_sync(0xffffffffu, mx0, 2));
        mx1 = fmaxf(mx1, __shfl_xor_sync(0xffffffffu, mx1, 1));
        mx1 = fmaxf(mx1, __shfl_xor_sync(0xffffffffu, mx1, 2));
        float mn0 = fmaxf(m0, mx0), mn1 = fmaxf(m1, mx1);
        float a0 = __expf(m0 - mn0), a1 = __expf(m1 - mn1);
        float s0 = 0.f, s1 = 0.f;
        #pragma unroll
        for (int q = 0; q < 8; q++) {
            c[q][0] = __expf(c[q][0] - mn0); s0 += c[q][0];
            c[q][1] = __expf(c[q][1] - mn0); s0 += c[q][1];
            c[q][2] = __expf(c[q][2] - mn1); s1 += c[q][2];
            c[q][3] = __expf(c[q][3] - mn1); s1 += c[q][3];
        }
        s0 += __shfl_xor_sync(0xffffffffu, s0, 1);
        s0 += __shfl_xor_sync(0xffffffffu, s0, 2);
        s1 += __shfl_xor_sync(0xffffffffu, s1, 1);
        s1 += __shfl_xor_sync(0xffffffffu, s1, 2);
        l0 = l0 * a0 + s0;
        l1 = l1 * a1 + s1;
        m0 = mn0; m1 = mn1;

        uint32_t pa[4][4];
        #pragma unroll
        for (int kt = 0; kt < 4; kt++) {
            pa[kt][0] = pk2(c[2 * kt][0],     c[2 * kt][1]);
            pa[kt][1] = pk2(c[2 * kt][2],     c[2 * kt][3]);
            pa[kt][2] = pk2(c[2 * kt + 1][0], c[2 * kt + 1][1]);
            pa[kt][3] = pk2(c[2 * kt + 1][2], c[2 * kt + 1][3]);
        }

        #pragma unroll
        for (int q = 0; q < 8; q++) {
            o[q][0] *= a0; o[q][1] *= a0;
            o[q][2] *= a1; o[q][3] *= a1;
        }
        #pragma unroll
        for (int kt = 0; kt < 4; kt++) {
            uint32_t vfr[8][2];
            #pragma unroll
            for (int ng = 0; ng < 4; ng++) {
                uint32_t t0, t1, t2, t3;
                ldm_x4t(t0, t1, t2, t3,
                        uV[s] + (kt * 16 + vRow) * AT_ROWB + ng * 32 + vColB);
                vfr[2 * ng][0] = t0; vfr[2 * ng][1] = t1;
                vfr[2 * ng + 1][0] = t2; vfr[2 * ng + 1][1] = t3;
            }
            #pragma unroll
            for (int q = 0; q < 8; q++)
                mma16816(o[q], pa[kt], vfr[q]);
        }
    }

    float inv0 = 1.f / l0, inv1 = 1.f / l1;
    #pragma unroll
    for (int q = 0; q < 8; q++) {
        int col = h * 64 + q * 8 + (lid & 3) * 2;
        if (rowg0 < SEQ)
            *(__half2*)&O[(size_t)(b * SEQ + rowg0) * D_MODEL + col] =
                __floats2half2_rn(o[q][0] * inv0, o[q][1] * inv0);
        if (rowg1 < SEQ)
            *(__half2*)&O[(size_t)(b * SEQ + rowg1) * D_MODEL + col] =
                __floats2half2_rn(o[q][2] * inv1, o[q][3] * inv1);
    }
}

// ---------------- launch ----------------
extern "C" void kernel_launch(void* const* d_in, const int* in_sizes, int n_in,
                              void* d_out, int out_size) {
    const float* x   = (const float*)d_in[0];
    const float* wq  = (const float*)d_in[1];
    const float* wk  = (const float*)d_in[2];
    const float* wv  = (const float*)d_in[3];
    const float* wo  = (const float*)d_in[4];
    const float* bo  = (const float*)d_in[5];
    const float* w1  = (const float*)d_in[6];
    const float* b1  = (const float*)d_in[7];
    const float* w2  = (const float*)d_in[8];
    const float* b2  = (const float*)d_in[9];
    const float* gg1 = (const float*)d_in[10];
    const float* be1 = (const float*)d_in[11];
    const float* gg2 = (const float*)d_in[12];
    const float* be2 = (const float*)d_in[13];
    float* out = (float*)d_out;

    float *px1;
    __half *pqkv, *pa16, *pb16, *pwqkv, *pwo, *pw1, *pw2;
    cudaGetSymbolAddress((void**)&px1,   g_x1);
    cudaGetSymbolAddress((void**)&pqkv,  g_qkv16);
    cudaGetSymbolAddress((void**)&pa16,  g_a16);
    cudaGetSymbolAddress((void**)&pb16,  g_b16);
    cudaGetSymbolAddress((void**)&pwqkv, g_wqkv16);
    cudaGetSymbolAddress((void**)&pwo,   g_wo16);
    cudaGetSymbolAddress((void**)&pw1,   g_w116);
    cudaGetSymbolAddress((void**)&pw2,   g_w216);

    cudaFuncSetAttribute(mma_gemm<0>, cudaFuncAttributeMaxDynamicSharedMemorySize, GEMM_SMEM);
    cudaFuncSetAttribute(mma_gemm<1>, cudaFuncAttributeMaxDynamicSharedMemorySize, GEMM_SMEM);
    cudaFuncSetAttribute(mma_gemm<2>, cudaFuncAttributeMaxDynamicSharedMemorySize, GEMM_SMEM);
    cudaFuncSetAttribute(mma_gemm<3>, cudaFuncAttributeMaxDynamicSharedMemorySize, GEMM_SMEM);

    // one fused weight-conversion launch (12288 tiles of 32x32)
    wcvt_all<<<12288, dim3(32, 8)>>>(wq, wk, wv, wo, w1, w2, pwqkv, pwo, pw1, pw2);

    dim3 gQKV(3 * D_MODEL / 128, (M_ROWS + 127) / 128);
    dim3 gD(D_MODEL / 128, (M_ROWS + 127) / 128);
    dim3 gF(D_FF / 128, (M_ROWS + 127) / 128);

    // 1. h16 = LN(x)
    ln16_kernel<<<M_ROWS, 256>>>(x, gg1, be1, pa16);
    // 2. QKV = h @ [Wq|Wk|Wv]
    mma_gemm<3><<<gQKV, 256, GEMM_SMEM>>>(pa16, pwqkv, nullptr, pqkv, M_ROWS, 3 * D_MODEL, D_MODEL, nullptr, nullptr);
    // 3. flash attention -> att16
    attn16_kernel<<<dim3(16, BATCH * N_HEADS), 128>>>(pqkv, pa16);
    // 4. x1 = x + att @ Wo + bo
    mma_gemm<1><<<gD, 256, GEMM_SMEM>>>(pa16, pwo, px1, nullptr, M_ROWS, D_MODEL, D_MODEL, bo, x);
    // 5. h2_16 = LN(x1)
    ln16_kernel<<<M_ROWS, 256>>>(px1, gg2, be2, pa16);
    // 6. ff16 = gelu(h2 @ W1 + b1)
    mma_gemm<2><<<gF, 256, GEMM_SMEM>>>(pa16, pw1, nullptr, pb16, M_ROWS, D_FF, D_MODEL, b1, nullptr);
    // 7. out = x1 + ff @ W2 + b2
    mma_gemm<1><<<gD, 256, GEMM_SMEM>>>(pb16, pw2, out, nullptr, M_ROWS, D_MODEL, D_FF, b2, px1);
}